// round 13
// baseline (speedup 1.0000x reference)
#include <cuda_runtime.h>
#include <cuda_bf16.h>
#include <cstdint>

#define F_IN 512
#define H1   8
#define D1   64      // H1*C1
#define OUT  40
#define NMAX 100000
#define EMAX 3200000
#define ETMAX (EMAX + NMAX)
#define NB_SCAN ((NMAX + 255) / 256)   // 391

// ---------------- scratch (device globals: allocation-free) ----------------
__device__ __align__(16) float g_h1 [NMAX * D1];
__device__ __align__(16) float g_as1[NMAX * H1];
__device__ __align__(16) float g_ad1[NMAX * H1];
__device__ __align__(16) __nv_bfloat162 g_h1b[NMAX * 32];  // bf16 copy of h1
__device__ __align__(16) float g_h2 [NMAX * D1];
__device__ __align__(16) float g_g2 [NMAX * OUT];
__device__ __align__(16) float g_as2[NMAX];
__device__ __align__(16) float g_ad2[NMAX];
__device__ __align__(16) float g_wT [D1 * F_IN];   // W1^T  [64][512]

__device__ int g_deg [NMAX];
__device__ int g_ptr [NMAX + 1];
__device__ int g_cur [NMAX];
__device__ int g_bsum[NB_SCAN];
__device__ int g_boff[NB_SCAN];
__device__ int g_csr [ETMAX];

// ---------------- tf32 / cp.async helpers ----------------
__device__ __forceinline__ uint32_t f2tf(float x) {
    uint32_t r;
    asm("cvt.rna.tf32.f32 %0, %1;" : "=r"(r) : "f"(x));
    return r;
}
__device__ __forceinline__ void mma_tf32(float c[4],
                                         uint32_t a0, uint32_t a1, uint32_t a2, uint32_t a3,
                                         uint32_t b0, uint32_t b1) {
    asm volatile("mma.sync.aligned.m16n8k8.row.col.f32.tf32.tf32.f32 "
                 "{%0,%1,%2,%3}, {%4,%5,%6,%7}, {%8,%9}, {%0,%1,%2,%3};"
                 : "+f"(c[0]), "+f"(c[1]), "+f"(c[2]), "+f"(c[3])
                 : "r"(a0), "r"(a1), "r"(a2), "r"(a3), "r"(b0), "r"(b1));
}
__device__ __forceinline__ void cpa16(uint32_t dst, const void* src) {
    asm volatile("cp.async.cg.shared.global [%0], [%1], 16;" :: "r"(dst), "l"(src));
}
__device__ __forceinline__ void cpa16p(uint32_t dst, const void* src, int ok) {
    int sz = ok ? 16 : 0;   // src-size 0 -> zero-fill
    asm volatile("cp.async.cg.shared.global [%0], [%1], 16, %2;"
                 :: "r"(dst), "l"(src), "r"(sz));
}

// ---------------- CSR build ----------------
__global__ void init_kernel(int N) {
    int i = blockIdx.x * blockDim.x + threadIdx.x;
    if (i < N) g_deg[i] = 1;
}
__global__ __launch_bounds__(256)
void hist_kernel(const int* __restrict__ ei, int E) {
    int e = blockIdx.x * blockDim.x + threadIdx.x;
    if (e < E) atomicAdd(&g_deg[ei[E + e]], 1);
}
__global__ __launch_bounds__(256)
void scan1_kernel(int N) {
    __shared__ int sd[256];
    int n = blockIdx.x * 256 + threadIdx.x;
    int v = (n < N) ? g_deg[n] : 0;
    sd[threadIdx.x] = v;
    __syncthreads();
    for (int off = 1; off < 256; off <<= 1) {
        int t = (threadIdx.x >= off) ? sd[threadIdx.x - off] : 0;
        __syncthreads();
        sd[threadIdx.x] += t;
        __syncthreads();
    }
    if (threadIdx.x == 255) g_bsum[blockIdx.x] = sd[255];
}
__global__ __launch_bounds__(512)
void scan2_kernel(int nb) {
    __shared__ int sd[512];
    int i = threadIdx.x;
    int v = (i < nb) ? g_bsum[i] : 0;
    sd[i] = v;
    __syncthreads();
    for (int off = 1; off < 512; off <<= 1) {
        int t = (i >= off) ? sd[i - off] : 0;
        __syncthreads();
        sd[i] += t;
        __syncthreads();
    }
    if (i < nb) g_boff[i] = sd[i] - v;
}
__global__ __launch_bounds__(256)
void scan3_kernel(int N, int Etot) {
    __shared__ int sd[256];
    int n = blockIdx.x * 256 + threadIdx.x;
    int v = (n < N) ? g_deg[n] : 0;
    sd[threadIdx.x] = v;
    __syncthreads();
    for (int off = 1; off < 256; off <<= 1) {
        int t = (threadIdx.x >= off) ? sd[threadIdx.x - off] : 0;
        __syncthreads();
        sd[threadIdx.x] += t;
        __syncthreads();
    }
    if (n < N) {
        int p = g_boff[blockIdx.x] + sd[threadIdx.x] - v;
        g_ptr[n] = p;
        g_cur[n] = p;
    }
    if (blockIdx.x == 0 && threadIdx.x == 0) g_ptr[N] = Etot;
}
__global__ __launch_bounds__(256)
void scatter_kernel(const int* __restrict__ ei, int E, int Etot) {
    int e = blockIdx.x * blockDim.x + threadIdx.x;
    if (e >= Etot) return;
    int s, d;
    if (e < E) { s = ei[e]; d = ei[E + e]; }
    else       { s = e - E; d = s; }
    int pos = atomicAdd(&g_cur[d], 1);
    g_csr[pos] = s;
}

// ---------------- transpose W1 -> wT[64][512] ----------------
__global__ void wt_kernel(const float* __restrict__ W) {
    int i = blockIdx.x * blockDim.x + threadIdx.x;
    if (i >= F_IN * D1) return;
    int k = i >> 6, n = i & 63;
    g_wT[n * F_IN + k] = W[i];
}

// ---------------- GEMM1 (3xTF32, cp.async 2-stage pipeline) ----------------
__global__ __launch_bounds__(256)
void gemm1_kernel(const float* __restrict__ x, int N) {
    __shared__ float sx[2][128][32];   // 32 KB
    __shared__ float sw[2][64][32];    // 16 KB

    int tid  = threadIdx.x;
    int wid  = tid >> 5;
    int l    = tid & 31;
    int gid  = l >> 2;
    int tig  = l & 3;
    int row0 = blockIdx.x * 128;
    int warp_m = (wid >> 1) * 32;
    int warp_n = (wid & 1) * 32;

    uint32_t sx_base = (uint32_t)__cvta_generic_to_shared(&sx[0][0][0]);
    uint32_t sw_base = (uint32_t)__cvta_generic_to_shared(&sw[0][0][0]);

    int xrow = tid >> 3;
    int xkq  = tid & 7;

    float acc[2][4][4];
#pragma unroll
    for (int mt = 0; mt < 2; mt++)
#pragma unroll
        for (int nt = 0; nt < 4; nt++)
#pragma unroll
            for (int r = 0; r < 4; r++) acc[mt][nt][r] = 0.0f;

    auto load_tiles = [&](int buf, int k0) {
#pragma unroll
        for (int i = 0; i < 4; i++) {
            int row  = xrow + i * 32;
            int grow = row0 + row;
            int ok   = grow < N;
            int gr   = ok ? grow : (N - 1);
            int kqs  = xkq ^ (row & 7);
            uint32_t dst = sx_base + (uint32_t)(((buf * 128 + row) * 32 + kqs * 4) * 4);
            cpa16p(dst, &x[(size_t)gr * F_IN + k0 + xkq * 4], ok);
        }
#pragma unroll
        for (int i = 0; i < 2; i++) {
            int row = xrow + i * 32;
            int kqs = xkq ^ (row & 7);
            uint32_t dst = sw_base + (uint32_t)(((buf * 64 + row) * 32 + kqs * 4) * 4);
            cpa16(dst, &g_wT[(size_t)row * F_IN + k0 + xkq * 4]);
        }
    };

    load_tiles(0, 0);
    asm volatile("cp.async.commit_group;");

    const int NT = F_IN / 32;   // 16
    for (int kt = 0; kt < NT; kt++) {
        int cur = kt & 1;
        if (kt + 1 < NT) {
            load_tiles(cur ^ 1, (kt + 1) * 32);
            asm volatile("cp.async.commit_group;");
            asm volatile("cp.async.wait_group 1;");
        } else {
            asm volatile("cp.async.wait_group 0;");
        }
        __syncthreads();

#pragma unroll
        for (int ks = 0; ks < 4; ks++) {
            int g0 = ks * 2, g1 = ks * 2 + 1;
            uint32_t ah[2][4], al[2][4];
#pragma unroll
            for (int mt = 0; mt < 2; mt++) {
                int rb = warp_m + mt * 16 + gid;
                int sw0 = (g0 ^ (rb & 7)) * 4 + tig;
                int sw1 = (g1 ^ (rb & 7)) * 4 + tig;
                float a0 = sx[cur][rb][sw0];
                float a1 = sx[cur][rb + 8][sw0];
                float a2 = sx[cur][rb][sw1];
                float a3 = sx[cur][rb + 8][sw1];
                ah[mt][0] = f2tf(a0); al[mt][0] = __float_as_uint(a0 - __uint_as_float(ah[mt][0]));
                ah[mt][1] = f2tf(a1); al[mt][1] = __float_as_uint(a1 - __uint_as_float(ah[mt][1]));
                ah[mt][2] = f2tf(a2); al[mt][2] = __float_as_uint(a2 - __uint_as_float(ah[mt][2]));
                ah[mt][3] = f2tf(a3); al[mt][3] = __float_as_uint(a3 - __uint_as_float(ah[mt][3]));
            }
            uint32_t bh[4][2], bl[4][2];
#pragma unroll
            for (int nt = 0; nt < 4; nt++) {
                int nb = warp_n + nt * 8 + gid;
                float b0 = sw[cur][nb][(g0 ^ (nb & 7)) * 4 + tig];
                float b1 = sw[cur][nb][(g1 ^ (nb & 7)) * 4 + tig];
                bh[nt][0] = f2tf(b0); bl[nt][0] = __float_as_uint(b0 - __uint_as_float(bh[nt][0]));
                bh[nt][1] = f2tf(b1); bl[nt][1] = __float_as_uint(b1 - __uint_as_float(bh[nt][1]));
            }
#pragma unroll
            for (int mt = 0; mt < 2; mt++)
#pragma unroll
                for (int nt = 0; nt < 4; nt++) {
                    mma_tf32(acc[mt][nt], ah[mt][0], ah[mt][1], ah[mt][2], ah[mt][3],
                             bh[nt][0], bh[nt][1]);
                    mma_tf32(acc[mt][nt], al[mt][0], al[mt][1], al[mt][2], al[mt][3],
                             bh[nt][0], bh[nt][1]);
                    mma_tf32(acc[mt][nt], ah[mt][0], ah[mt][1], ah[mt][2], ah[mt][3],
                             bl[nt][0], bl[nt][1]);
                }
        }
        __syncthreads();
    }

#pragma unroll
    for (int mt = 0; mt < 2; mt++) {
        int r0 = row0 + warp_m + mt * 16 + gid;
        int r1 = r0 + 8;
#pragma unroll
        for (int nt = 0; nt < 4; nt++) {
            int col = warp_n + nt * 8 + 2 * tig;
            if (r0 < N) *(float2*)&g_h1[(size_t)r0 * D1 + col]
                            = make_float2(acc[mt][nt][0], acc[mt][nt][1]);
            if (r1 < N) *(float2*)&g_h1[(size_t)r1 * D1 + col]
                            = make_float2(acc[mt][nt][2], acc[mt][nt][3]);
        }
    }
}

// ---------------- alpha1: dots + bf16 conversion of h1 ----------------
__global__ void alpha1_kernel(const float* __restrict__ a_src,
                              const float* __restrict__ a_dst, int N) {
    int i = blockIdx.x * blockDim.x + threadIdx.x;
    if (i >= N * H1) return;
    int h = i & 7;
    int n = i >> 3;
    const float4* hp = (const float4*)&g_h1[(size_t)n * D1 + h * 8];
    float4 v0 = hp[0], v1 = hp[1];
    const float4* asv = (const float4*)&a_src[h * 8];
    const float4* adv = (const float4*)&a_dst[h * 8];
    float4 s0 = asv[0], s1 = asv[1];
    float4 d0 = adv[0], d1 = adv[1];
    g_as1[i] = v0.x * s0.x + v0.y * s0.y + v0.z * s0.z + v0.w * s0.w
             + v1.x * s1.x + v1.y * s1.y + v1.z * s1.z + v1.w * s1.w;
    g_ad1[i] = v0.x * d0.x + v0.y * d0.y + v0.z * d0.z + v0.w * d0.w
             + v1.x * d1.x + v1.y * d1.y + v1.z * d1.z + v1.w * d1.w;
    // bf16 copy (cols h*8..h*8+7 -> slots n*32 + h*4 .. +3), 16B aligned store
    __nv_bfloat162 b0 = __floats2bfloat162_rn(v0.x, v0.y);
    __nv_bfloat162 b1 = __floats2bfloat162_rn(v0.z, v0.w);
    __nv_bfloat162 b2 = __floats2bfloat162_rn(v1.x, v1.y);
    __nv_bfloat162 b3 = __floats2bfloat162_rn(v1.z, v1.w);
    uint4 packed = make_uint4(*(uint32_t*)&b0, *(uint32_t*)&b1,
                              *(uint32_t*)&b2, *(uint32_t*)&b3);
    *(uint4*)&g_h1b[(size_t)n * 32 + h * 4] = packed;
}

// ---------------- gather layer 1: warp/node, lane l owns cols 2l,2l+1 ------
// Features read from bf16 copy (128B/edge), logits/accum in f32.
__global__ __launch_bounds__(256)
void gather1_kernel(const float* __restrict__ b1, int N) {
    int w = (blockIdx.x * blockDim.x + threadIdx.x) >> 5;
    if (w >= N) return;
    int l = threadIdx.x & 31;
    int d = w;
    int beg = g_ptr[d], end = g_ptr[d + 1];
    int h = l >> 2;

    float ad = g_ad1[d * H1 + h];

    float accx = 0.f, accy = 0.f, den = 0.f;
    int i = beg;
    for (; i + 2 <= end; i += 2) {
        int s0 = g_csr[i], s1 = g_csr[i + 1];
        float as0 = g_as1[s0 * H1 + h];
        float as1v = g_as1[s1 * H1 + h];
        float2 f0 = __bfloat1622float2(g_h1b[(size_t)s0 * 32 + l]);
        float2 f1 = __bfloat1622float2(g_h1b[(size_t)s1 * 32 + l]);

        float t0 = as0 + ad;  t0 = (t0 > 0.f) ? t0 : 0.2f * t0;
        float t1 = as1v + ad; t1 = (t1 > 0.f) ? t1 : 0.2f * t1;
        float e0 = __expf(t0), e1 = __expf(t1);

        accx += e0 * f0.x + e1 * f1.x;
        accy += e0 * f0.y + e1 * f1.y;
        den  += e0 + e1;
    }
    if (i < end) {
        int s = g_csr[i];
        float as = g_as1[s * H1 + h];
        float t = as + ad;  t = (t > 0.f) ? t : 0.2f * t;
        float ex = __expf(t);
        float2 f = __bfloat1622float2(g_h1b[(size_t)s * 32 + l]);
        accx += ex * f.x;
        accy += ex * f.y;
        den  += ex;
    }
    float inv = 1.0f / (den + 1e-16f);
    float vx = accx * inv + b1[2 * l];
    float vy = accy * inv + b1[2 * l + 1];
    vx = (vx > 0.f) ? vx : (__expf(vx) - 1.f);
    vy = (vy > 0.f) ? vy : (__expf(vy) - 1.f);
    *(float2*)&g_h2[(size_t)d * D1 + 2 * l] = make_float2(vx, vy);
}

// ---------------- GEMM2 + alpha2: g2[N,40] = h2[N,64]@W2[64,40] ------------
__global__ __launch_bounds__(256)
void gemm2_kernel(const float* __restrict__ W2,
                  const float* __restrict__ a_src2,
                  const float* __restrict__ a_dst2, int N) {
    __shared__ float sh[64 * 65];
    __shared__ float sw2[64 * OUT];

    int tid = threadIdx.x;
    int n0  = blockIdx.x * 64;

    for (int t = tid; t < 64 * D1; t += 256) {
        int r = t >> 6, c = t & 63;
        int gn = n0 + r;
        sh[r * 65 + c] = (gn < N) ? g_h2[(size_t)gn * D1 + c] : 0.0f;
    }
    for (int t = tid; t < D1 * OUT; t += 256) sw2[t] = W2[t];
    __syncthreads();

    int r = tid >> 2;
    int q = tid & 3;
    float acc[10];
#pragma unroll
    for (int j = 0; j < 10; j++) acc[j] = 0.0f;

#pragma unroll 8
    for (int k = 0; k < D1; k++) {
        float a = sh[r * 65 + k];
#pragma unroll
        for (int j = 0; j < 10; j++)
            acc[j] += a * sw2[k * OUT + q * 10 + j];
    }

    int gn = n0 + r;
    float ps = 0.0f, pd = 0.0f;
#pragma unroll
    for (int j = 0; j < 10; j++) {
        int c = q * 10 + j;
        ps += acc[j] * __ldg(&a_src2[c]);
        pd += acc[j] * __ldg(&a_dst2[c]);
        if (gn < N) g_g2[(size_t)gn * OUT + c] = acc[j];
    }
    ps += __shfl_down_sync(0xffffffffu, ps, 1, 4);
    ps += __shfl_down_sync(0xffffffffu, ps, 2, 4);
    pd += __shfl_down_sync(0xffffffffu, pd, 1, 4);
    pd += __shfl_down_sync(0xffffffffu, pd, 2, 4);
    if (q == 0 && gn < N) { g_as2[gn] = ps; g_ad2[gn] = pd; }
}

// ---------------- gather layer 2: warp/node, lanes 0-19 own cols 2l,2l+1 ---
__global__ __launch_bounds__(256)
void gather2_kernel(const float* __restrict__ b2, float* __restrict__ out, int N) {
    int w = (blockIdx.x * blockDim.x + threadIdx.x) >> 5;
    if (w >= N) return;
    int l = threadIdx.x & 31;
    int d = w;
    int beg = g_ptr[d], end = g_ptr[d + 1];
    bool act = (l < 20);

    float ad = g_ad2[d];
    float accx = 0.f, accy = 0.f, den = 0.f;
    int i = beg;
    for (; i + 2 <= end; i += 2) {
        int s0 = g_csr[i], s1 = g_csr[i + 1];
        float a0 = g_as2[s0], a1 = g_as2[s1];
        float2 f0 = make_float2(0.f, 0.f), f1 = make_float2(0.f, 0.f);
        if (act) {
            f0 = *(const float2*)&g_g2[(size_t)s0 * OUT + 2 * l];
            f1 = *(const float2*)&g_g2[(size_t)s1 * OUT + 2 * l];
        }
        float t0 = a0 + ad; t0 = (t0 > 0.f) ? t0 : 0.2f * t0;
        float t1 = a1 + ad; t1 = (t1 > 0.f) ? t1 : 0.2f * t1;
        float e0 = __expf(t0), e1 = __expf(t1);
        accx += e0 * f0.x + e1 * f1.x;
        accy += e0 * f0.y + e1 * f1.y;
        den  += e0 + e1;
    }
    if (i < end) {
        int s = g_csr[i];
        float t = g_as2[s] + ad;
        t = (t > 0.f) ? t : 0.2f * t;
        float ex = __expf(t);
        if (act) {
            float2 f = *(const float2*)&g_g2[(size_t)s * OUT + 2 * l];
            accx += ex * f.x;
            accy += ex * f.y;
        }
        den += ex;
    }
    if (act) {
        float inv = 1.0f / (den + 1e-16f);
        out[(size_t)d * OUT + 2 * l]     = accx * inv + b2[2 * l];
        out[(size_t)d * OUT + 2 * l + 1] = accy * inv + b2[2 * l + 1];
    }
}

// ---------------- launch ----------------
extern "C" void kernel_launch(void* const* d_in, const int* in_sizes, int n_in,
                              void* d_out, int out_size) {
    const float* x      = (const float*)d_in[0];
    const int*   ei     = (const int*)d_in[1];
    const float* W1     = (const float*)d_in[2];
    const float* a_src1 = (const float*)d_in[3];
    const float* a_dst1 = (const float*)d_in[4];
    const float* b1     = (const float*)d_in[5];
    const float* W2     = (const float*)d_in[6];
    const float* a_src2 = (const float*)d_in[7];
    const float* a_dst2 = (const float*)d_in[8];
    const float* b2     = (const float*)d_in[9];
    float* out = (float*)d_out;

    int N    = in_sizes[0] / F_IN;       // 100000
    int E    = in_sizes[1] / 2;          // 3200000
    int Etot = E + N;
    int nb   = (N + 255) / 256;

    wt_kernel<<<(F_IN * D1 + 255) / 256, 256>>>(W1);          // 0
    init_kernel<<<(N + 255) / 256, 256>>>(N);                 // 1
    hist_kernel<<<(E + 255) / 256, 256>>>(ei, E);             // 2
    gemm1_kernel<<<(N + 127) / 128, 256>>>(x, N);             // 3  <- profiled
    scan1_kernel<<<nb, 256>>>(N);                             // 4
    scan2_kernel<<<1, 512>>>(nb);                             // 5
    scan3_kernel<<<nb, 256>>>(N, Etot);                       // 6
    scatter_kernel<<<(Etot + 255) / 256, 256>>>(ei, E, Etot); // 7
    alpha1_kernel<<<(N * H1 + 255) / 256, 256>>>(a_src1, a_dst1, N); // 8
    gather1_kernel<<<(N * 32 + 255) / 256, 256>>>(b1, N);     // 9
    gemm2_kernel<<<(N + 63) / 64, 256>>>(W2, a_src2, a_dst2, N); // 10
    gather2_kernel<<<(N * 32 + 255) / 256, 256>>>(b2, out, N);   // 11
}

// round 14
// speedup vs baseline: 1.0604x; 1.0604x over previous
#include <cuda_runtime.h>
#include <cstdint>

#define F_IN 512
#define H1   8
#define D1   64      // H1*C1
#define OUT  40
#define NMAX 100000
#define EMAX 3200000
#define ETMAX (EMAX + NMAX)
#define NB_SCAN ((NMAX + 255) / 256)   // 391

// ---------------- scratch (device globals: allocation-free) ----------------
__device__ __align__(16) float g_h1 [NMAX * D1];
__device__ __align__(16) float g_as1[NMAX * H1];
__device__ __align__(16) float g_ad1[NMAX * H1];
__device__ __align__(16) float g_h2 [NMAX * D1];
__device__ __align__(16) float g_g2 [NMAX * OUT];
__device__ __align__(16) float g_as2[NMAX];
__device__ __align__(16) float g_ad2[NMAX];
__device__ __align__(16) float g_wT [D1 * F_IN];   // W1^T  [64][512]

__device__ int g_deg [NMAX];
__device__ int g_ptr [NMAX + 1];
__device__ int g_cur [NMAX];
__device__ int g_bsum[NB_SCAN];
__device__ int g_boff[NB_SCAN];
__device__ int g_csr [ETMAX];

// ---------------- tf32 / cp.async helpers ----------------
__device__ __forceinline__ uint32_t f2tf(float x) {
    uint32_t r;
    asm("cvt.rna.tf32.f32 %0, %1;" : "=r"(r) : "f"(x));
    return r;
}
__device__ __forceinline__ void mma_tf32(float c[4],
                                         uint32_t a0, uint32_t a1, uint32_t a2, uint32_t a3,
                                         uint32_t b0, uint32_t b1) {
    asm volatile("mma.sync.aligned.m16n8k8.row.col.f32.tf32.tf32.f32 "
                 "{%0,%1,%2,%3}, {%4,%5,%6,%7}, {%8,%9}, {%0,%1,%2,%3};"
                 : "+f"(c[0]), "+f"(c[1]), "+f"(c[2]), "+f"(c[3])
                 : "r"(a0), "r"(a1), "r"(a2), "r"(a3), "r"(b0), "r"(b1));
}
__device__ __forceinline__ void cpa16(uint32_t dst, const void* src) {
    asm volatile("cp.async.cg.shared.global [%0], [%1], 16;" :: "r"(dst), "l"(src));
}
__device__ __forceinline__ void cpa16p(uint32_t dst, const void* src, int ok) {
    int sz = ok ? 16 : 0;   // src-size 0 -> zero-fill
    asm volatile("cp.async.cg.shared.global [%0], [%1], 16, %2;"
                 :: "r"(dst), "l"(src), "r"(sz));
}

// ---------------- CSR build ----------------
__global__ void init_kernel(int N) {
    int i = blockIdx.x * blockDim.x + threadIdx.x;
    if (i < N) g_deg[i] = 1;
}
__global__ __launch_bounds__(256)
void hist_kernel(const int* __restrict__ ei, int E) {
    int e = blockIdx.x * blockDim.x + threadIdx.x;
    if (e < E) atomicAdd(&g_deg[ei[E + e]], 1);
}
__global__ __launch_bounds__(256)
void scan1_kernel(int N) {
    __shared__ int sd[256];
    int n = blockIdx.x * 256 + threadIdx.x;
    int v = (n < N) ? g_deg[n] : 0;
    sd[threadIdx.x] = v;
    __syncthreads();
    for (int off = 1; off < 256; off <<= 1) {
        int t = (threadIdx.x >= off) ? sd[threadIdx.x - off] : 0;
        __syncthreads();
        sd[threadIdx.x] += t;
        __syncthreads();
    }
    if (threadIdx.x == 255) g_bsum[blockIdx.x] = sd[255];
}
__global__ __launch_bounds__(512)
void scan2_kernel(int nb) {
    __shared__ int sd[512];
    int i = threadIdx.x;
    int v = (i < nb) ? g_bsum[i] : 0;
    sd[i] = v;
    __syncthreads();
    for (int off = 1; off < 512; off <<= 1) {
        int t = (i >= off) ? sd[i - off] : 0;
        __syncthreads();
        sd[i] += t;
        __syncthreads();
    }
    if (i < nb) g_boff[i] = sd[i] - v;
}
__global__ __launch_bounds__(256)
void scan3_kernel(int N, int Etot) {
    __shared__ int sd[256];
    int n = blockIdx.x * 256 + threadIdx.x;
    int v = (n < N) ? g_deg[n] : 0;
    sd[threadIdx.x] = v;
    __syncthreads();
    for (int off = 1; off < 256; off <<= 1) {
        int t = (threadIdx.x >= off) ? sd[threadIdx.x - off] : 0;
        __syncthreads();
        sd[threadIdx.x] += t;
        __syncthreads();
    }
    if (n < N) {
        int p = g_boff[blockIdx.x] + sd[threadIdx.x] - v;
        g_ptr[n] = p;
        g_cur[n] = p;
    }
    if (blockIdx.x == 0 && threadIdx.x == 0) g_ptr[N] = Etot;
}
__global__ __launch_bounds__(256)
void scatter_kernel(const int* __restrict__ ei, int E, int Etot) {
    int e = blockIdx.x * blockDim.x + threadIdx.x;
    if (e >= Etot) return;
    int s, d;
    if (e < E) { s = ei[e]; d = ei[E + e]; }
    else       { s = e - E; d = s; }
    int pos = atomicAdd(&g_cur[d], 1);
    g_csr[pos] = s;
}

// ---------------- transpose W1 -> wT[64][512] ----------------
__global__ void wt_kernel(const float* __restrict__ W) {
    int i = blockIdx.x * blockDim.x + threadIdx.x;
    if (i >= F_IN * D1) return;
    int k = i >> 6, n = i & 63;
    g_wT[n * F_IN + k] = W[i];
}

// ---------------- GEMM1 (3xTF32, cp.async 2-stage pipeline) ----------------
__global__ __launch_bounds__(256)
void gemm1_kernel(const float* __restrict__ x, int N) {
    __shared__ float sx[2][128][32];   // 32 KB
    __shared__ float sw[2][64][32];    // 16 KB

    int tid  = threadIdx.x;
    int wid  = tid >> 5;
    int l    = tid & 31;
    int gid  = l >> 2;
    int tig  = l & 3;
    int row0 = blockIdx.x * 128;
    int warp_m = (wid >> 1) * 32;
    int warp_n = (wid & 1) * 32;

    uint32_t sx_base = (uint32_t)__cvta_generic_to_shared(&sx[0][0][0]);
    uint32_t sw_base = (uint32_t)__cvta_generic_to_shared(&sw[0][0][0]);

    int xrow = tid >> 3;
    int xkq  = tid & 7;

    float acc[2][4][4];
#pragma unroll
    for (int mt = 0; mt < 2; mt++)
#pragma unroll
        for (int nt = 0; nt < 4; nt++)
#pragma unroll
            for (int r = 0; r < 4; r++) acc[mt][nt][r] = 0.0f;

    auto load_tiles = [&](int buf, int k0) {
#pragma unroll
        for (int i = 0; i < 4; i++) {
            int row  = xrow + i * 32;
            int grow = row0 + row;
            int ok   = grow < N;
            int gr   = ok ? grow : (N - 1);
            int kqs  = xkq ^ (row & 7);
            uint32_t dst = sx_base + (uint32_t)(((buf * 128 + row) * 32 + kqs * 4) * 4);
            cpa16p(dst, &x[(size_t)gr * F_IN + k0 + xkq * 4], ok);
        }
#pragma unroll
        for (int i = 0; i < 2; i++) {
            int row = xrow + i * 32;
            int kqs = xkq ^ (row & 7);
            uint32_t dst = sw_base + (uint32_t)(((buf * 64 + row) * 32 + kqs * 4) * 4);
            cpa16(dst, &g_wT[(size_t)row * F_IN + k0 + xkq * 4]);
        }
    };

    load_tiles(0, 0);
    asm volatile("cp.async.commit_group;");

    const int NT = F_IN / 32;   // 16
    for (int kt = 0; kt < NT; kt++) {
        int cur = kt & 1;
        if (kt + 1 < NT) {
            load_tiles(cur ^ 1, (kt + 1) * 32);
            asm volatile("cp.async.commit_group;");
            asm volatile("cp.async.wait_group 1;");
        } else {
            asm volatile("cp.async.wait_group 0;");
        }
        __syncthreads();

#pragma unroll
        for (int ks = 0; ks < 4; ks++) {
            int g0 = ks * 2, g1 = ks * 2 + 1;
            uint32_t ah[2][4], al[2][4];
#pragma unroll
            for (int mt = 0; mt < 2; mt++) {
                int rb = warp_m + mt * 16 + gid;
                int sw0 = (g0 ^ (rb & 7)) * 4 + tig;
                int sw1 = (g1 ^ (rb & 7)) * 4 + tig;
                float a0 = sx[cur][rb][sw0];
                float a1 = sx[cur][rb + 8][sw0];
                float a2 = sx[cur][rb][sw1];
                float a3 = sx[cur][rb + 8][sw1];
                ah[mt][0] = f2tf(a0); al[mt][0] = __float_as_uint(a0 - __uint_as_float(ah[mt][0]));
                ah[mt][1] = f2tf(a1); al[mt][1] = __float_as_uint(a1 - __uint_as_float(ah[mt][1]));
                ah[mt][2] = f2tf(a2); al[mt][2] = __float_as_uint(a2 - __uint_as_float(ah[mt][2]));
                ah[mt][3] = f2tf(a3); al[mt][3] = __float_as_uint(a3 - __uint_as_float(ah[mt][3]));
            }
            uint32_t bh[4][2], bl[4][2];
#pragma unroll
            for (int nt = 0; nt < 4; nt++) {
                int nb = warp_n + nt * 8 + gid;
                float b0 = sw[cur][nb][(g0 ^ (nb & 7)) * 4 + tig];
                float b1 = sw[cur][nb][(g1 ^ (nb & 7)) * 4 + tig];
                bh[nt][0] = f2tf(b0); bl[nt][0] = __float_as_uint(b0 - __uint_as_float(bh[nt][0]));
                bh[nt][1] = f2tf(b1); bl[nt][1] = __float_as_uint(b1 - __uint_as_float(bh[nt][1]));
            }
#pragma unroll
            for (int mt = 0; mt < 2; mt++)
#pragma unroll
                for (int nt = 0; nt < 4; nt++) {
                    mma_tf32(acc[mt][nt], ah[mt][0], ah[mt][1], ah[mt][2], ah[mt][3],
                             bh[nt][0], bh[nt][1]);
                    mma_tf32(acc[mt][nt], al[mt][0], al[mt][1], al[mt][2], al[mt][3],
                             bh[nt][0], bh[nt][1]);
                    mma_tf32(acc[mt][nt], ah[mt][0], ah[mt][1], ah[mt][2], ah[mt][3],
                             bl[nt][0], bl[nt][1]);
                }
        }
        __syncthreads();
    }

#pragma unroll
    for (int mt = 0; mt < 2; mt++) {
        int r0 = row0 + warp_m + mt * 16 + gid;
        int r1 = r0 + 8;
#pragma unroll
        for (int nt = 0; nt < 4; nt++) {
            int col = warp_n + nt * 8 + 2 * tig;
            if (r0 < N) *(float2*)&g_h1[(size_t)r0 * D1 + col]
                            = make_float2(acc[mt][nt][0], acc[mt][nt][1]);
            if (r1 < N) *(float2*)&g_h1[(size_t)r1 * D1 + col]
                            = make_float2(acc[mt][nt][2], acc[mt][nt][3]);
        }
    }
}

// ---------------- alpha1: per (node, head) dot products ----------------
__global__ void alpha1_kernel(const float* __restrict__ a_src,
                              const float* __restrict__ a_dst, int N) {
    int i = blockIdx.x * blockDim.x + threadIdx.x;
    if (i >= N * H1) return;
    int h = i & 7;
    const float4* hp = (const float4*)&g_h1[(size_t)(i >> 3) * D1 + h * 8];
    float4 v0 = hp[0], v1 = hp[1];
    const float4* asv = (const float4*)&a_src[h * 8];
    const float4* adv = (const float4*)&a_dst[h * 8];
    float4 s0 = asv[0], s1 = asv[1];
    float4 d0 = adv[0], d1 = adv[1];
    g_as1[i] = v0.x * s0.x + v0.y * s0.y + v0.z * s0.z + v0.w * s0.w
             + v1.x * s1.x + v1.y * s1.y + v1.z * s1.z + v1.w * s1.w;
    g_ad1[i] = v0.x * d0.x + v0.y * d0.y + v0.z * d0.z + v0.w * d0.w
             + v1.x * d1.x + v1.y * d1.y + v1.z * d1.z + v1.w * d1.w;
}

// ---------------- gather layer 1: warp/node, 4-wide unroll -----------------
// lane l owns cols 2l,2l+1; head h = l>>2. One float2 LDG/edge + scalar alpha.
__global__ __launch_bounds__(256)
void gather1_kernel(const float* __restrict__ b1, int N) {
    int w = (blockIdx.x * blockDim.x + threadIdx.x) >> 5;
    if (w >= N) return;
    int l = threadIdx.x & 31;
    int d = w;
    int beg = g_ptr[d], end = g_ptr[d + 1];
    int h = l >> 2;

    float ad = g_ad1[d * H1 + h];

    float accx = 0.f, accy = 0.f, den = 0.f;
    int i = beg;
    for (; i + 4 <= end; i += 4) {
        int s0 = g_csr[i],     s1 = g_csr[i + 1];
        int s2 = g_csr[i + 2], s3 = g_csr[i + 3];
        float a0 = g_as1[s0 * H1 + h];
        float a1 = g_as1[s1 * H1 + h];
        float a2 = g_as1[s2 * H1 + h];
        float a3 = g_as1[s3 * H1 + h];
        float2 f0 = *(const float2*)&g_h1[(size_t)s0 * D1 + 2 * l];
        float2 f1 = *(const float2*)&g_h1[(size_t)s1 * D1 + 2 * l];
        float2 f2 = *(const float2*)&g_h1[(size_t)s2 * D1 + 2 * l];
        float2 f3 = *(const float2*)&g_h1[(size_t)s3 * D1 + 2 * l];

        float t0 = a0 + ad; t0 = (t0 > 0.f) ? t0 : 0.2f * t0;
        float t1 = a1 + ad; t1 = (t1 > 0.f) ? t1 : 0.2f * t1;
        float t2 = a2 + ad; t2 = (t2 > 0.f) ? t2 : 0.2f * t2;
        float t3 = a3 + ad; t3 = (t3 > 0.f) ? t3 : 0.2f * t3;
        float e0 = __expf(t0), e1 = __expf(t1), e2 = __expf(t2), e3 = __expf(t3);

        accx += e0 * f0.x + e1 * f1.x + e2 * f2.x + e3 * f3.x;
        accy += e0 * f0.y + e1 * f1.y + e2 * f2.y + e3 * f3.y;
        den  += e0 + e1 + e2 + e3;
    }
    for (; i < end; i++) {
        int s = g_csr[i];
        float as = g_as1[s * H1 + h];
        float t = as + ad;  t = (t > 0.f) ? t : 0.2f * t;
        float ex = __expf(t);
        float2 f = *(const float2*)&g_h1[(size_t)s * D1 + 2 * l];
        accx += ex * f.x;
        accy += ex * f.y;
        den  += ex;
    }
    float inv = 1.0f / (den + 1e-16f);
    float vx = accx * inv + b1[2 * l];
    float vy = accy * inv + b1[2 * l + 1];
    vx = (vx > 0.f) ? vx : (__expf(vx) - 1.f);
    vy = (vy > 0.f) ? vy : (__expf(vy) - 1.f);
    *(float2*)&g_h2[(size_t)d * D1 + 2 * l] = make_float2(vx, vy);
}

// ---------------- GEMM2 + alpha2: g2[N,40] = h2[N,64]@W2[64,40] ------------
__global__ __launch_bounds__(256)
void gemm2_kernel(const float* __restrict__ W2,
                  const float* __restrict__ a_src2,
                  const float* __restrict__ a_dst2, int N) {
    __shared__ float sh[64 * 65];
    __shared__ float sw2[64 * OUT];

    int tid = threadIdx.x;
    int n0  = blockIdx.x * 64;

    for (int t = tid; t < 64 * D1; t += 256) {
        int r = t >> 6, c = t & 63;
        int gn = n0 + r;
        sh[r * 65 + c] = (gn < N) ? g_h2[(size_t)gn * D1 + c] : 0.0f;
    }
    for (int t = tid; t < D1 * OUT; t += 256) sw2[t] = W2[t];
    __syncthreads();

    int r = tid >> 2;
    int q = tid & 3;
    float acc[10];
#pragma unroll
    for (int j = 0; j < 10; j++) acc[j] = 0.0f;

#pragma unroll 8
    for (int k = 0; k < D1; k++) {
        float a = sh[r * 65 + k];
#pragma unroll
        for (int j = 0; j < 10; j++)
            acc[j] += a * sw2[k * OUT + q * 10 + j];
    }

    int gn = n0 + r;
    float ps = 0.0f, pd = 0.0f;
#pragma unroll
    for (int j = 0; j < 10; j++) {
        int c = q * 10 + j;
        ps += acc[j] * __ldg(&a_src2[c]);
        pd += acc[j] * __ldg(&a_dst2[c]);
        if (gn < N) g_g2[(size_t)gn * OUT + c] = acc[j];
    }
    ps += __shfl_down_sync(0xffffffffu, ps, 1, 4);
    ps += __shfl_down_sync(0xffffffffu, ps, 2, 4);
    pd += __shfl_down_sync(0xffffffffu, pd, 1, 4);
    pd += __shfl_down_sync(0xffffffffu, pd, 2, 4);
    if (q == 0 && gn < N) { g_as2[gn] = ps; g_ad2[gn] = pd; }
}

// ---------------- gather layer 2: warp/node, 4-wide, lanes 0-19 active -----
__global__ __launch_bounds__(256)
void gather2_kernel(const float* __restrict__ b2, float* __restrict__ out, int N) {
    int w = (blockIdx.x * blockDim.x + threadIdx.x) >> 5;
    if (w >= N) return;
    int l = threadIdx.x & 31;
    int d = w;
    int beg = g_ptr[d], end = g_ptr[d + 1];
    bool act = (l < 20);

    float ad = g_ad2[d];
    float accx = 0.f, accy = 0.f, den = 0.f;
    int i = beg;
    for (; i + 4 <= end; i += 4) {
        int s0 = g_csr[i],     s1 = g_csr[i + 1];
        int s2 = g_csr[i + 2], s3 = g_csr[i + 3];
        float a0 = g_as2[s0], a1 = g_as2[s1], a2 = g_as2[s2], a3 = g_as2[s3];
        float2 f0 = make_float2(0.f, 0.f), f1 = make_float2(0.f, 0.f);
        float2 f2 = make_float2(0.f, 0.f), f3 = make_float2(0.f, 0.f);
        if (act) {
            f0 = *(const float2*)&g_g2[(size_t)s0 * OUT + 2 * l];
            f1 = *(const float2*)&g_g2[(size_t)s1 * OUT + 2 * l];
            f2 = *(const float2*)&g_g2[(size_t)s2 * OUT + 2 * l];
            f3 = *(const float2*)&g_g2[(size_t)s3 * OUT + 2 * l];
        }
        float t0 = a0 + ad; t0 = (t0 > 0.f) ? t0 : 0.2f * t0;
        float t1 = a1 + ad; t1 = (t1 > 0.f) ? t1 : 0.2f * t1;
        float t2 = a2 + ad; t2 = (t2 > 0.f) ? t2 : 0.2f * t2;
        float t3 = a3 + ad; t3 = (t3 > 0.f) ? t3 : 0.2f * t3;
        float e0 = __expf(t0), e1 = __expf(t1), e2 = __expf(t2), e3 = __expf(t3);
        accx += e0 * f0.x + e1 * f1.x + e2 * f2.x + e3 * f3.x;
        accy += e0 * f0.y + e1 * f1.y + e2 * f2.y + e3 * f3.y;
        den  += e0 + e1 + e2 + e3;
    }
    for (; i < end; i++) {
        int s = g_csr[i];
        float t = g_as2[s] + ad;
        t = (t > 0.f) ? t : 0.2f * t;
        float ex = __expf(t);
        if (act) {
            float2 f = *(const float2*)&g_g2[(size_t)s * OUT + 2 * l];
            accx += ex * f.x;
            accy += ex * f.y;
        }
        den += ex;
    }
    if (act) {
        float inv = 1.0f / (den + 1e-16f);
        out[(size_t)d * OUT + 2 * l]     = accx * inv + b2[2 * l];
        out[(size_t)d * OUT + 2 * l + 1] = accy * inv + b2[2 * l + 1];
    }
}

// ---------------- launch ----------------
extern "C" void kernel_launch(void* const* d_in, const int* in_sizes, int n_in,
                              void* d_out, int out_size) {
    const float* x      = (const float*)d_in[0];
    const int*   ei     = (const int*)d_in[1];
    const float* W1     = (const float*)d_in[2];
    const float* a_src1 = (const float*)d_in[3];
    const float* a_dst1 = (const float*)d_in[4];
    const float* b1     = (const float*)d_in[5];
    const float* W2     = (const float*)d_in[6];
    const float* a_src2 = (const float*)d_in[7];
    const float* a_dst2 = (const float*)d_in[8];
    const float* b2     = (const float*)d_in[9];
    float* out = (float*)d_out;

    int N    = in_sizes[0] / F_IN;       // 100000
    int E    = in_sizes[1] / 2;          // 3200000
    int Etot = E + N;
    int nb   = (N + 255) / 256;

    wt_kernel<<<(F_IN * D1 + 255) / 256, 256>>>(W1);          // 0
    init_kernel<<<(N + 255) / 256, 256>>>(N);                 // 1
    hist_kernel<<<(E + 255) / 256, 256>>>(ei, E);             // 2
    gemm1_kernel<<<(N + 127) / 128, 256>>>(x, N);             // 3  <- profiled
    scan1_kernel<<<nb, 256>>>(N);                             // 4
    scan2_kernel<<<1, 512>>>(nb);                             // 5
    scan3_kernel<<<nb, 256>>>(N, Etot);                       // 6
    scatter_kernel<<<(Etot + 255) / 256, 256>>>(ei, E, Etot); // 7
    alpha1_kernel<<<(N * H1 + 255) / 256, 256>>>(a_src1, a_dst1, N); // 8
    gather1_kernel<<<(N * 32 + 255) / 256, 256>>>(b1, N);     // 9
    gemm2_kernel<<<(N + 63) / 64, 256>>>(W2, a_src2, a_dst2, N); // 10
    gather2_kernel<<<(N * 32 + 255) / 256, 256>>>(b2, out, N);   // 11
}

// round 15
// speedup vs baseline: 1.2473x; 1.1763x over previous
#include <cuda_runtime.h>
#include <cstdint>

#define F_IN 512
#define H1   8
#define D1   64      // H1*C1
#define OUT  40
#define NMAX 100000
#define EMAX 3200000
#define ETMAX (EMAX + NMAX)
#define NB_SCAN ((NMAX + 255) / 256)   // 391

// ---------------- scratch (device globals: allocation-free) ----------------
__device__ __align__(16) float g_h1 [NMAX * D1];
__device__ __align__(16) float g_as1[NMAX * H1];
__device__ __align__(16) float g_ad1[NMAX * H1];
__device__ __align__(16) float g_h2 [NMAX * D1];
__device__ __align__(16) float g_g2 [NMAX * OUT];
__device__ __align__(16) float g_as2[NMAX];
__device__ __align__(16) float g_ad2[NMAX];
__device__ __align__(16) float g_wT [D1 * F_IN];   // W1^T  [64][512]

__device__ int g_deg [NMAX];
__device__ int g_ptr [NMAX + 1];
__device__ int g_cur [NMAX];
__device__ int g_bsum[NB_SCAN];
__device__ int g_boff[NB_SCAN];
__device__ int g_csr [ETMAX];

// ---------------- tf32 / cp.async helpers ----------------
__device__ __forceinline__ uint32_t f2tf(float x) {
    uint32_t r;
    asm("cvt.rna.tf32.f32 %0, %1;" : "=r"(r) : "f"(x));
    return r;
}
__device__ __forceinline__ void mma_tf32(float c[4],
                                         uint32_t a0, uint32_t a1, uint32_t a2, uint32_t a3,
                                         uint32_t b0, uint32_t b1) {
    asm volatile("mma.sync.aligned.m16n8k8.row.col.f32.tf32.tf32.f32 "
                 "{%0,%1,%2,%3}, {%4,%5,%6,%7}, {%8,%9}, {%0,%1,%2,%3};"
                 : "+f"(c[0]), "+f"(c[1]), "+f"(c[2]), "+f"(c[3])
                 : "r"(a0), "r"(a1), "r"(a2), "r"(a3), "r"(b0), "r"(b1));
}
__device__ __forceinline__ void cpa16(uint32_t dst, const void* src) {
    asm volatile("cp.async.cg.shared.global [%0], [%1], 16;" :: "r"(dst), "l"(src));
}
__device__ __forceinline__ void cpa16p(uint32_t dst, const void* src, int ok) {
    int sz = ok ? 16 : 0;   // src-size 0 -> zero-fill
    asm volatile("cp.async.cg.shared.global [%0], [%1], 16, %2;"
                 :: "r"(dst), "l"(src), "r"(sz));
}

// ---------------- CSR build ----------------
__global__ void init_kernel(int N) {
    int i = blockIdx.x * blockDim.x + threadIdx.x;
    if (i < N) g_deg[i] = 1;
}
__global__ __launch_bounds__(256)
void hist_kernel(const int* __restrict__ ei, int E) {
    int e = blockIdx.x * blockDim.x + threadIdx.x;
    if (e < E) atomicAdd(&g_deg[ei[E + e]], 1);
}
__global__ __launch_bounds__(256)
void scan1_kernel(int N) {
    __shared__ int sd[256];
    int n = blockIdx.x * 256 + threadIdx.x;
    int v = (n < N) ? g_deg[n] : 0;
    sd[threadIdx.x] = v;
    __syncthreads();
    for (int off = 1; off < 256; off <<= 1) {
        int t = (threadIdx.x >= off) ? sd[threadIdx.x - off] : 0;
        __syncthreads();
        sd[threadIdx.x] += t;
        __syncthreads();
    }
    if (threadIdx.x == 255) g_bsum[blockIdx.x] = sd[255];
}
__global__ __launch_bounds__(512)
void scan2_kernel(int nb) {
    __shared__ int sd[512];
    int i = threadIdx.x;
    int v = (i < nb) ? g_bsum[i] : 0;
    sd[i] = v;
    __syncthreads();
    for (int off = 1; off < 512; off <<= 1) {
        int t = (i >= off) ? sd[i - off] : 0;
        __syncthreads();
        sd[i] += t;
        __syncthreads();
    }
    if (i < nb) g_boff[i] = sd[i] - v;
}
__global__ __launch_bounds__(256)
void scan3_kernel(int N, int Etot) {
    __shared__ int sd[256];
    int n = blockIdx.x * 256 + threadIdx.x;
    int v = (n < N) ? g_deg[n] : 0;
    sd[threadIdx.x] = v;
    __syncthreads();
    for (int off = 1; off < 256; off <<= 1) {
        int t = (threadIdx.x >= off) ? sd[threadIdx.x - off] : 0;
        __syncthreads();
        sd[threadIdx.x] += t;
        __syncthreads();
    }
    if (n < N) {
        int p = g_boff[blockIdx.x] + sd[threadIdx.x] - v;
        g_ptr[n] = p;
        g_cur[n] = p;
    }
    if (blockIdx.x == 0 && threadIdx.x == 0) g_ptr[N] = Etot;
}
__global__ __launch_bounds__(256)
void scatter_kernel(const int* __restrict__ ei, int E, int Etot) {
    int e = blockIdx.x * blockDim.x + threadIdx.x;
    if (e >= Etot) return;
    int s, d;
    if (e < E) { s = ei[e]; d = ei[E + e]; }
    else       { s = e - E; d = s; }
    int pos = atomicAdd(&g_cur[d], 1);
    g_csr[pos] = s;
}

// ---------------- transpose W1 -> wT[64][512] ----------------
__global__ void wt_kernel(const float* __restrict__ W) {
    int i = blockIdx.x * blockDim.x + threadIdx.x;
    if (i >= F_IN * D1) return;
    int k = i >> 6, n = i & 63;
    g_wT[n * F_IN + k] = W[i];
}

// ---------------- GEMM1 (3xTF32, cp.async 2-stage pipeline) ----------------
__global__ __launch_bounds__(256)
void gemm1_kernel(const float* __restrict__ x, int N) {
    __shared__ float sx[2][128][32];   // 32 KB
    __shared__ float sw[2][64][32];    // 16 KB

    int tid  = threadIdx.x;
    int wid  = tid >> 5;
    int l    = tid & 31;
    int gid  = l >> 2;
    int tig  = l & 3;
    int row0 = blockIdx.x * 128;
    int warp_m = (wid >> 1) * 32;
    int warp_n = (wid & 1) * 32;

    uint32_t sx_base = (uint32_t)__cvta_generic_to_shared(&sx[0][0][0]);
    uint32_t sw_base = (uint32_t)__cvta_generic_to_shared(&sw[0][0][0]);

    int xrow = tid >> 3;
    int xkq  = tid & 7;

    float acc[2][4][4];
#pragma unroll
    for (int mt = 0; mt < 2; mt++)
#pragma unroll
        for (int nt = 0; nt < 4; nt++)
#pragma unroll
            for (int r = 0; r < 4; r++) acc[mt][nt][r] = 0.0f;

    auto load_tiles = [&](int buf, int k0) {
#pragma unroll
        for (int i = 0; i < 4; i++) {
            int row  = xrow + i * 32;
            int grow = row0 + row;
            int ok   = grow < N;
            int gr   = ok ? grow : (N - 1);
            int kqs  = xkq ^ (row & 7);
            uint32_t dst = sx_base + (uint32_t)(((buf * 128 + row) * 32 + kqs * 4) * 4);
            cpa16p(dst, &x[(size_t)gr * F_IN + k0 + xkq * 4], ok);
        }
#pragma unroll
        for (int i = 0; i < 2; i++) {
            int row = xrow + i * 32;
            int kqs = xkq ^ (row & 7);
            uint32_t dst = sw_base + (uint32_t)(((buf * 64 + row) * 32 + kqs * 4) * 4);
            cpa16(dst, &g_wT[(size_t)row * F_IN + k0 + xkq * 4]);
        }
    };

    load_tiles(0, 0);
    asm volatile("cp.async.commit_group;");

    const int NT = F_IN / 32;   // 16
    for (int kt = 0; kt < NT; kt++) {
        int cur = kt & 1;
        if (kt + 1 < NT) {
            load_tiles(cur ^ 1, (kt + 1) * 32);
            asm volatile("cp.async.commit_group;");
            asm volatile("cp.async.wait_group 1;");
        } else {
            asm volatile("cp.async.wait_group 0;");
        }
        __syncthreads();

#pragma unroll
        for (int ks = 0; ks < 4; ks++) {
            int g0 = ks * 2, g1 = ks * 2 + 1;
            uint32_t ah[2][4], al[2][4];
#pragma unroll
            for (int mt = 0; mt < 2; mt++) {
                int rb = warp_m + mt * 16 + gid;
                int sw0 = (g0 ^ (rb & 7)) * 4 + tig;
                int sw1 = (g1 ^ (rb & 7)) * 4 + tig;
                float a0 = sx[cur][rb][sw0];
                float a1 = sx[cur][rb + 8][sw0];
                float a2 = sx[cur][rb][sw1];
                float a3 = sx[cur][rb + 8][sw1];
                ah[mt][0] = f2tf(a0); al[mt][0] = __float_as_uint(a0 - __uint_as_float(ah[mt][0]));
                ah[mt][1] = f2tf(a1); al[mt][1] = __float_as_uint(a1 - __uint_as_float(ah[mt][1]));
                ah[mt][2] = f2tf(a2); al[mt][2] = __float_as_uint(a2 - __uint_as_float(ah[mt][2]));
                ah[mt][3] = f2tf(a3); al[mt][3] = __float_as_uint(a3 - __uint_as_float(ah[mt][3]));
            }
            uint32_t bh[4][2], bl[4][2];
#pragma unroll
            for (int nt = 0; nt < 4; nt++) {
                int nb = warp_n + nt * 8 + gid;
                float b0 = sw[cur][nb][(g0 ^ (nb & 7)) * 4 + tig];
                float b1 = sw[cur][nb][(g1 ^ (nb & 7)) * 4 + tig];
                bh[nt][0] = f2tf(b0); bl[nt][0] = __float_as_uint(b0 - __uint_as_float(bh[nt][0]));
                bh[nt][1] = f2tf(b1); bl[nt][1] = __float_as_uint(b1 - __uint_as_float(bh[nt][1]));
            }
#pragma unroll
            for (int mt = 0; mt < 2; mt++)
#pragma unroll
                for (int nt = 0; nt < 4; nt++) {
                    mma_tf32(acc[mt][nt], ah[mt][0], ah[mt][1], ah[mt][2], ah[mt][3],
                             bh[nt][0], bh[nt][1]);
                    mma_tf32(acc[mt][nt], al[mt][0], al[mt][1], al[mt][2], al[mt][3],
                             bh[nt][0], bh[nt][1]);
                    mma_tf32(acc[mt][nt], ah[mt][0], ah[mt][1], ah[mt][2], ah[mt][3],
                             bl[nt][0], bl[nt][1]);
                }
        }
        __syncthreads();
    }

#pragma unroll
    for (int mt = 0; mt < 2; mt++) {
        int r0 = row0 + warp_m + mt * 16 + gid;
        int r1 = r0 + 8;
#pragma unroll
        for (int nt = 0; nt < 4; nt++) {
            int col = warp_n + nt * 8 + 2 * tig;
            if (r0 < N) *(float2*)&g_h1[(size_t)r0 * D1 + col]
                            = make_float2(acc[mt][nt][0], acc[mt][nt][1]);
            if (r1 < N) *(float2*)&g_h1[(size_t)r1 * D1 + col]
                            = make_float2(acc[mt][nt][2], acc[mt][nt][3]);
        }
    }
}

// ---------------- alpha1: per (node, head) dot products ----------------
__global__ void alpha1_kernel(const float* __restrict__ a_src,
                              const float* __restrict__ a_dst, int N) {
    int i = blockIdx.x * blockDim.x + threadIdx.x;
    if (i >= N * H1) return;
    int h = i & 7;
    const float4* hp = (const float4*)&g_h1[(size_t)(i >> 3) * D1 + h * 8];
    float4 v0 = hp[0], v1 = hp[1];
    const float4* asv = (const float4*)&a_src[h * 8];
    const float4* adv = (const float4*)&a_dst[h * 8];
    float4 s0 = asv[0], s1 = asv[1];
    float4 d0 = adv[0], d1 = adv[1];
    g_as1[i] = v0.x * s0.x + v0.y * s0.y + v0.z * s0.z + v0.w * s0.w
             + v1.x * s1.x + v1.y * s1.y + v1.z * s1.z + v1.w * s1.w;
    g_ad1[i] = v0.x * d0.x + v0.y * d0.y + v0.z * d0.z + v0.w * d0.w
             + v1.x * d1.x + v1.y * d1.y + v1.z * d1.z + v1.w * d1.w;
}

// ---------------- gather layer 1: warp/node, 2 edges per step --------------
// lanes 0-15 = edge A, lanes 16-31 = edge B; lane q owns cols 4q..4q+3.
// head h = q>>1. Halves combined via shfl_xor(16) at the end.
__global__ __launch_bounds__(256)
void gather1_kernel(const float* __restrict__ b1, int N) {
    int w = (blockIdx.x * blockDim.x + threadIdx.x) >> 5;
    if (w >= N) return;
    int l    = threadIdx.x & 31;
    int half = l >> 4;
    int q    = l & 15;
    int h    = q >> 1;
    int d    = w;
    int beg = g_ptr[d], end = g_ptr[d + 1];

    float ad = g_ad1[d * H1 + h];

    float ax = 0.f, ay = 0.f, az = 0.f, aw = 0.f, den = 0.f;
    int i = beg;
    for (; i + 4 <= end; i += 4) {             // 2 steps x 2 edges
        int s0 = g_csr[i + half];
        int s1 = g_csr[i + 2 + half];
        float a0 = g_as1[s0 * H1 + h];
        float a1 = g_as1[s1 * H1 + h];
        float4 f0 = *(const float4*)&g_h1[(size_t)s0 * D1 + 4 * q];
        float4 f1 = *(const float4*)&g_h1[(size_t)s1 * D1 + 4 * q];
        float t0 = a0 + ad; t0 = (t0 > 0.f) ? t0 : 0.2f * t0;
        float t1 = a1 + ad; t1 = (t1 > 0.f) ? t1 : 0.2f * t1;
        float e0 = __expf(t0), e1 = __expf(t1);
        ax += e0 * f0.x + e1 * f1.x;
        ay += e0 * f0.y + e1 * f1.y;
        az += e0 * f0.z + e1 * f1.z;
        aw += e0 * f0.w + e1 * f1.w;
        den += e0 + e1;
    }
    for (; i < end; i += 2) {                  // tail: 1 or 2 edges
        int has2 = (i + 1 < end) ? 1 : 0;
        int s = g_csr[i + (half & has2)];
        float a = g_as1[s * H1 + h];
        float4 f = *(const float4*)&g_h1[(size_t)s * D1 + 4 * q];
        float t = a + ad; t = (t > 0.f) ? t : 0.2f * t;
        float ex = __expf(t);
        if (half && !has2) ex = 0.f;
        ax += ex * f.x; ay += ex * f.y; az += ex * f.z; aw += ex * f.w;
        den += ex;
    }
    ax  += __shfl_xor_sync(0xffffffffu, ax, 16);
    ay  += __shfl_xor_sync(0xffffffffu, ay, 16);
    az  += __shfl_xor_sync(0xffffffffu, az, 16);
    aw  += __shfl_xor_sync(0xffffffffu, aw, 16);
    den += __shfl_xor_sync(0xffffffffu, den, 16);
    if (half == 0) {
        float inv = 1.0f / (den + 1e-16f);
        float4 bb = *(const float4*)&b1[4 * q];
        float vx = ax * inv + bb.x;
        float vy = ay * inv + bb.y;
        float vz = az * inv + bb.z;
        float vw = aw * inv + bb.w;
        vx = (vx > 0.f) ? vx : (__expf(vx) - 1.f);
        vy = (vy > 0.f) ? vy : (__expf(vy) - 1.f);
        vz = (vz > 0.f) ? vz : (__expf(vz) - 1.f);
        vw = (vw > 0.f) ? vw : (__expf(vw) - 1.f);
        *(float4*)&g_h2[(size_t)d * D1 + 4 * q] = make_float4(vx, vy, vz, vw);
    }
}

// ---------------- GEMM2 + alpha2: g2[N,40] = h2[N,64]@W2[64,40] ------------
__global__ __launch_bounds__(256)
void gemm2_kernel(const float* __restrict__ W2,
                  const float* __restrict__ a_src2,
                  const float* __restrict__ a_dst2, int N) {
    __shared__ float sh[64 * 65];
    __shared__ float sw2[64 * OUT];

    int tid = threadIdx.x;
    int n0  = blockIdx.x * 64;

    for (int t = tid; t < 64 * D1; t += 256) {
        int r = t >> 6, c = t & 63;
        int gn = n0 + r;
        sh[r * 65 + c] = (gn < N) ? g_h2[(size_t)gn * D1 + c] : 0.0f;
    }
    for (int t = tid; t < D1 * OUT; t += 256) sw2[t] = W2[t];
    __syncthreads();

    int r = tid >> 2;
    int q = tid & 3;
    float acc[10];
#pragma unroll
    for (int j = 0; j < 10; j++) acc[j] = 0.0f;

#pragma unroll 8
    for (int k = 0; k < D1; k++) {
        float a = sh[r * 65 + k];
#pragma unroll
        for (int j = 0; j < 10; j++)
            acc[j] += a * sw2[k * OUT + q * 10 + j];
    }

    int gn = n0 + r;
    float ps = 0.0f, pd = 0.0f;
#pragma unroll
    for (int j = 0; j < 10; j++) {
        int c = q * 10 + j;
        ps += acc[j] * __ldg(&a_src2[c]);
        pd += acc[j] * __ldg(&a_dst2[c]);
        if (gn < N) g_g2[(size_t)gn * OUT + c] = acc[j];
    }
    ps += __shfl_down_sync(0xffffffffu, ps, 1, 4);
    ps += __shfl_down_sync(0xffffffffu, ps, 2, 4);
    pd += __shfl_down_sync(0xffffffffu, pd, 1, 4);
    pd += __shfl_down_sync(0xffffffffu, pd, 2, 4);
    if (q == 0 && gn < N) { g_as2[gn] = ps; g_ad2[gn] = pd; }
}

// ---------------- gather layer 2: warp/node, 3 edges per step --------------
// lanes 0-29: group g = l/10 handles edge g; lane owns cols 4q..4q+3 (q=l%10).
// Groups combined via shfl_down(10) + shfl_down(20); lanes 0-9 write.
__global__ __launch_bounds__(256)
void gather2_kernel(const float* __restrict__ b2, float* __restrict__ out, int N) {
    int w = (blockIdx.x * blockDim.x + threadIdx.x) >> 5;
    if (w >= N) return;
    int l = threadIdx.x & 31;
    bool act = (l < 30);
    int g = act ? (l / 10) : 0;
    int q = act ? (l - g * 10) : 0;
    int d = w;
    int beg = g_ptr[d], end = g_ptr[d + 1];

    float ad = g_ad2[d];
    float ax = 0.f, ay = 0.f, az = 0.f, aw = 0.f, den = 0.f;
    int i = beg;
    for (; i + 6 <= end; i += 6) {             // 2 steps x 3 edges
        int s0 = g_csr[i + g];
        int s1 = g_csr[i + 3 + g];
        float a0 = g_as2[s0], a1 = g_as2[s1];
        float4 f0 = *(const float4*)&g_g2[(size_t)s0 * OUT + 4 * q];
        float4 f1 = *(const float4*)&g_g2[(size_t)s1 * OUT + 4 * q];
        float t0 = a0 + ad; t0 = (t0 > 0.f) ? t0 : 0.2f * t0;
        float t1 = a1 + ad; t1 = (t1 > 0.f) ? t1 : 0.2f * t1;
        float e0 = __expf(t0), e1 = __expf(t1);
        if (!act) { e0 = 0.f; e1 = 0.f; }
        ax += e0 * f0.x + e1 * f1.x;
        ay += e0 * f0.y + e1 * f1.y;
        az += e0 * f0.z + e1 * f1.z;
        aw += e0 * f0.w + e1 * f1.w;
        den += e0 + e1;
    }
    for (; i < end; i += 3) {                  // tail: 1..5 edges in steps of <=3
        int rem = end - i;
        int ok = act && (g < rem);
        int s = g_csr[i + (ok ? g : 0)];
        float a = g_as2[s];
        float4 f = *(const float4*)&g_g2[(size_t)s * OUT + 4 * q];
        float t = a + ad; t = (t > 0.f) ? t : 0.2f * t;
        float ex = __expf(t);
        if (!ok) ex = 0.f;
        ax += ex * f.x; ay += ex * f.y; az += ex * f.z; aw += ex * f.w;
        den += ex;
    }
    // combine 3 groups -> lanes 0-9
    float bx1 = __shfl_down_sync(0xffffffffu, ax, 10);
    float bx2 = __shfl_down_sync(0xffffffffu, ax, 20);
    float by1 = __shfl_down_sync(0xffffffffu, ay, 10);
    float by2 = __shfl_down_sync(0xffffffffu, ay, 20);
    float bz1 = __shfl_down_sync(0xffffffffu, az, 10);
    float bz2 = __shfl_down_sync(0xffffffffu, az, 20);
    float bw1 = __shfl_down_sync(0xffffffffu, aw, 10);
    float bw2 = __shfl_down_sync(0xffffffffu, aw, 20);
    float bd1 = __shfl_down_sync(0xffffffffu, den, 10);
    float bd2 = __shfl_down_sync(0xffffffffu, den, 20);
    if (l < 10) {
        ax += bx1 + bx2; ay += by1 + by2; az += bz1 + bz2; aw += bw1 + bw2;
        den += bd1 + bd2;
        float inv = 1.0f / (den + 1e-16f);
        float4 bb = *(const float4*)&b2[4 * q];
        out[(size_t)d * OUT + 4 * q + 0] = ax * inv + bb.x;
        out[(size_t)d * OUT + 4 * q + 1] = ay * inv + bb.y;
        out[(size_t)d * OUT + 4 * q + 2] = az * inv + bb.z;
        out[(size_t)d * OUT + 4 * q + 3] = aw * inv + bb.w;
    }
}

// ---------------- launch ----------------
extern "C" void kernel_launch(void* const* d_in, const int* in_sizes, int n_in,
                              void* d_out, int out_size) {
    const float* x      = (const float*)d_in[0];
    const int*   ei     = (const int*)d_in[1];
    const float* W1     = (const float*)d_in[2];
    const float* a_src1 = (const float*)d_in[3];
    const float* a_dst1 = (const float*)d_in[4];
    const float* b1     = (const float*)d_in[5];
    const float* W2     = (const float*)d_in[6];
    const float* a_src2 = (const float*)d_in[7];
    const float* a_dst2 = (const float*)d_in[8];
    const float* b2     = (const float*)d_in[9];
    float* out = (float*)d_out;

    int N    = in_sizes[0] / F_IN;       // 100000
    int E    = in_sizes[1] / 2;          // 3200000
    int Etot = E + N;
    int nb   = (N + 255) / 256;

    wt_kernel<<<(F_IN * D1 + 255) / 256, 256>>>(W1);          // 0
    init_kernel<<<(N + 255) / 256, 256>>>(N);                 // 1
    hist_kernel<<<(E + 255) / 256, 256>>>(ei, E);             // 2
    gemm1_kernel<<<(N + 127) / 128, 256>>>(x, N);             // 3  <- profiled
    scan1_kernel<<<nb, 256>>>(N);                             // 4
    scan2_kernel<<<1, 512>>>(nb);                             // 5
    scan3_kernel<<<nb, 256>>>(N, Etot);                       // 6
    scatter_kernel<<<(Etot + 255) / 256, 256>>>(ei, E, Etot); // 7
    alpha1_kernel<<<(N * H1 + 255) / 256, 256>>>(a_src1, a_dst1, N); // 8
    gather1_kernel<<<(N * 32 + 255) / 256, 256>>>(b1, N);     // 9
    gemm2_kernel<<<(N + 63) / 64, 256>>>(W2, a_src2, a_dst2, N); // 10
    gather2_kernel<<<(N * 32 + 255) / 256, 256>>>(b2, out, N);   // 11
}

// round 16
// speedup vs baseline: 1.3597x; 1.0901x over previous
#include <cuda_runtime.h>
#include <cstdint>

#define F_IN 512
#define H1   8
#define D1   64      // H1*C1
#define OUT  40
#define NMAX 100000
#define EMAX 3200000
#define ETMAX (EMAX + NMAX)
#define NB_SCAN ((NMAX + 255) / 256)   // 391

// ---------------- scratch (device globals: allocation-free) ----------------
__device__ __align__(16) float g_h1 [NMAX * D1];
__device__ __align__(16) float g_as1[NMAX * H1];
__device__ __align__(16) float g_ad1[NMAX * H1];
__device__ __align__(16) float g_h2 [NMAX * D1];
__device__ __align__(16) float g_g2 [NMAX * OUT];
__device__ __align__(16) float g_as2[NMAX];
__device__ __align__(16) float g_ad2[NMAX];
__device__ __align__(16) float g_wT [D1 * F_IN];   // W1^T  [64][512]

__device__ int g_deg [NMAX];
__device__ int g_ptr [NMAX + 1];
__device__ int g_cur [NMAX];
__device__ int g_bsum[NB_SCAN];
__device__ int g_boff[NB_SCAN];
__device__ int g_csr [ETMAX];

// ---------------- tf32 / cp.async helpers ----------------
__device__ __forceinline__ uint32_t f2tf(float x) {
    uint32_t r;
    asm("cvt.rna.tf32.f32 %0, %1;" : "=r"(r) : "f"(x));
    return r;
}
__device__ __forceinline__ void mma_tf32(float c[4],
                                         uint32_t a0, uint32_t a1, uint32_t a2, uint32_t a3,
                                         uint32_t b0, uint32_t b1) {
    asm volatile("mma.sync.aligned.m16n8k8.row.col.f32.tf32.tf32.f32 "
                 "{%0,%1,%2,%3}, {%4,%5,%6,%7}, {%8,%9}, {%0,%1,%2,%3};"
                 : "+f"(c[0]), "+f"(c[1]), "+f"(c[2]), "+f"(c[3])
                 : "r"(a0), "r"(a1), "r"(a2), "r"(a3), "r"(b0), "r"(b1));
}
__device__ __forceinline__ void cpa16(uint32_t dst, const void* src) {
    asm volatile("cp.async.cg.shared.global [%0], [%1], 16;" :: "r"(dst), "l"(src));
}
__device__ __forceinline__ void cpa16p(uint32_t dst, const void* src, int ok) {
    int sz = ok ? 16 : 0;   // src-size 0 -> zero-fill
    asm volatile("cp.async.cg.shared.global [%0], [%1], 16, %2;"
                 :: "r"(dst), "l"(src), "r"(sz));
}

// ---------------- CSR build ----------------
__global__ void init_kernel(int N) {
    int i = blockIdx.x * blockDim.x + threadIdx.x;
    if (i < N) g_deg[i] = 1;
}
__global__ __launch_bounds__(256)
void hist_kernel(const int* __restrict__ ei, int E) {
    int e = blockIdx.x * blockDim.x + threadIdx.x;
    if (e < E) atomicAdd(&g_deg[ei[E + e]], 1);
}
__global__ __launch_bounds__(256)
void scan1_kernel(int N) {
    __shared__ int sd[256];
    int n = blockIdx.x * 256 + threadIdx.x;
    int v = (n < N) ? g_deg[n] : 0;
    sd[threadIdx.x] = v;
    __syncthreads();
    for (int off = 1; off < 256; off <<= 1) {
        int t = (threadIdx.x >= off) ? sd[threadIdx.x - off] : 0;
        __syncthreads();
        sd[threadIdx.x] += t;
        __syncthreads();
    }
    if (threadIdx.x == 255) g_bsum[blockIdx.x] = sd[255];
}
__global__ __launch_bounds__(512)
void scan2_kernel(int nb) {
    __shared__ int sd[512];
    int i = threadIdx.x;
    int v = (i < nb) ? g_bsum[i] : 0;
    sd[i] = v;
    __syncthreads();
    for (int off = 1; off < 512; off <<= 1) {
        int t = (i >= off) ? sd[i - off] : 0;
        __syncthreads();
        sd[i] += t;
        __syncthreads();
    }
    if (i < nb) g_boff[i] = sd[i] - v;
}
__global__ __launch_bounds__(256)
void scan3_kernel(int N, int Etot) {
    __shared__ int sd[256];
    int n = blockIdx.x * 256 + threadIdx.x;
    int v = (n < N) ? g_deg[n] : 0;
    sd[threadIdx.x] = v;
    __syncthreads();
    for (int off = 1; off < 256; off <<= 1) {
        int t = (threadIdx.x >= off) ? sd[threadIdx.x - off] : 0;
        __syncthreads();
        sd[threadIdx.x] += t;
        __syncthreads();
    }
    if (n < N) {
        int p = g_boff[blockIdx.x] + sd[threadIdx.x] - v;
        g_ptr[n] = p;
        g_cur[n] = p;
    }
    if (blockIdx.x == 0 && threadIdx.x == 0) g_ptr[N] = Etot;
}
__global__ __launch_bounds__(256)
void scatter_kernel(const int* __restrict__ ei, int E, int Etot) {
    int e = blockIdx.x * blockDim.x + threadIdx.x;
    if (e >= Etot) return;
    int s, d;
    if (e < E) { s = ei[e]; d = ei[E + e]; }
    else       { s = e - E; d = s; }
    int pos = atomicAdd(&g_cur[d], 1);
    g_csr[pos] = s;
}

// ---------------- transpose W1 -> wT[64][512] ----------------
__global__ void wt_kernel(const float* __restrict__ W) {
    int i = blockIdx.x * blockDim.x + threadIdx.x;
    if (i >= F_IN * D1) return;
    int k = i >> 6, n = i & 63;
    g_wT[n * F_IN + k] = W[i];
}

// ---------------- GEMM1 (2-term split-TF32, cp.async 2-stage) --------------
// h1 = x @ W1: result = ah*bh + ah*bl (A-lo term dropped; err ~2^-12 per dot).
__global__ __launch_bounds__(256)
void gemm1_kernel(const float* __restrict__ x, int N) {
    __shared__ float sx[2][128][32];   // 32 KB
    __shared__ float sw[2][64][32];    // 16 KB

    int tid  = threadIdx.x;
    int wid  = tid >> 5;
    int l    = tid & 31;
    int gid  = l >> 2;
    int tig  = l & 3;
    int row0 = blockIdx.x * 128;
    int warp_m = (wid >> 1) * 32;
    int warp_n = (wid & 1) * 32;

    uint32_t sx_base = (uint32_t)__cvta_generic_to_shared(&sx[0][0][0]);
    uint32_t sw_base = (uint32_t)__cvta_generic_to_shared(&sw[0][0][0]);

    int xrow = tid >> 3;
    int xkq  = tid & 7;

    float acc[2][4][4];
#pragma unroll
    for (int mt = 0; mt < 2; mt++)
#pragma unroll
        for (int nt = 0; nt < 4; nt++)
#pragma unroll
            for (int r = 0; r < 4; r++) acc[mt][nt][r] = 0.0f;

    auto load_tiles = [&](int buf, int k0) {
#pragma unroll
        for (int i = 0; i < 4; i++) {
            int row  = xrow + i * 32;
            int grow = row0 + row;
            int ok   = grow < N;
            int gr   = ok ? grow : (N - 1);
            int kqs  = xkq ^ (row & 7);
            uint32_t dst = sx_base + (uint32_t)(((buf * 128 + row) * 32 + kqs * 4) * 4);
            cpa16p(dst, &x[(size_t)gr * F_IN + k0 + xkq * 4], ok);
        }
#pragma unroll
        for (int i = 0; i < 2; i++) {
            int row = xrow + i * 32;
            int kqs = xkq ^ (row & 7);
            uint32_t dst = sw_base + (uint32_t)(((buf * 64 + row) * 32 + kqs * 4) * 4);
            cpa16(dst, &g_wT[(size_t)row * F_IN + k0 + xkq * 4]);
        }
    };

    load_tiles(0, 0);
    asm volatile("cp.async.commit_group;");

    const int NT = F_IN / 32;   // 16
    for (int kt = 0; kt < NT; kt++) {
        int cur = kt & 1;
        if (kt + 1 < NT) {
            load_tiles(cur ^ 1, (kt + 1) * 32);
            asm volatile("cp.async.commit_group;");
            asm volatile("cp.async.wait_group 1;");
        } else {
            asm volatile("cp.async.wait_group 0;");
        }
        __syncthreads();

#pragma unroll
        for (int ks = 0; ks < 4; ks++) {
            int g0 = ks * 2, g1 = ks * 2 + 1;
            uint32_t ah[2][4];
#pragma unroll
            for (int mt = 0; mt < 2; mt++) {
                int rb = warp_m + mt * 16 + gid;
                int sw0 = (g0 ^ (rb & 7)) * 4 + tig;
                int sw1 = (g1 ^ (rb & 7)) * 4 + tig;
                ah[mt][0] = f2tf(sx[cur][rb][sw0]);
                ah[mt][1] = f2tf(sx[cur][rb + 8][sw0]);
                ah[mt][2] = f2tf(sx[cur][rb][sw1]);
                ah[mt][3] = f2tf(sx[cur][rb + 8][sw1]);
            }
            uint32_t bh[4][2], bl[4][2];
#pragma unroll
            for (int nt = 0; nt < 4; nt++) {
                int nb = warp_n + nt * 8 + gid;
                float b0 = sw[cur][nb][(g0 ^ (nb & 7)) * 4 + tig];
                float b1 = sw[cur][nb][(g1 ^ (nb & 7)) * 4 + tig];
                bh[nt][0] = f2tf(b0); bl[nt][0] = __float_as_uint(b0 - __uint_as_float(bh[nt][0]));
                bh[nt][1] = f2tf(b1); bl[nt][1] = __float_as_uint(b1 - __uint_as_float(bh[nt][1]));
            }
#pragma unroll
            for (int mt = 0; mt < 2; mt++)
#pragma unroll
                for (int nt = 0; nt < 4; nt++) {
                    mma_tf32(acc[mt][nt], ah[mt][0], ah[mt][1], ah[mt][2], ah[mt][3],
                             bh[nt][0], bh[nt][1]);
                    mma_tf32(acc[mt][nt], ah[mt][0], ah[mt][1], ah[mt][2], ah[mt][3],
                             bl[nt][0], bl[nt][1]);
                }
        }
        __syncthreads();
    }

#pragma unroll
    for (int mt = 0; mt < 2; mt++) {
        int r0 = row0 + warp_m + mt * 16 + gid;
        int r1 = r0 + 8;
#pragma unroll
        for (int nt = 0; nt < 4; nt++) {
            int col = warp_n + nt * 8 + 2 * tig;
            if (r0 < N) *(float2*)&g_h1[(size_t)r0 * D1 + col]
                            = make_float2(acc[mt][nt][0], acc[mt][nt][1]);
            if (r1 < N) *(float2*)&g_h1[(size_t)r1 * D1 + col]
                            = make_float2(acc[mt][nt][2], acc[mt][nt][3]);
        }
    }
}

// ---------------- alpha1: per (node, head) dot products ----------------
__global__ void alpha1_kernel(const float* __restrict__ a_src,
                              const float* __restrict__ a_dst, int N) {
    int i = blockIdx.x * blockDim.x + threadIdx.x;
    if (i >= N * H1) return;
    int h = i & 7;
    const float4* hp = (const float4*)&g_h1[(size_t)(i >> 3) * D1 + h * 8];
    float4 v0 = hp[0], v1 = hp[1];
    const float4* asv = (const float4*)&a_src[h * 8];
    const float4* adv = (const float4*)&a_dst[h * 8];
    float4 s0 = asv[0], s1 = asv[1];
    float4 d0 = adv[0], d1 = adv[1];
    g_as1[i] = v0.x * s0.x + v0.y * s0.y + v0.z * s0.z + v0.w * s0.w
             + v1.x * s1.x + v1.y * s1.y + v1.z * s1.z + v1.w * s1.w;
    g_ad1[i] = v0.x * d0.x + v0.y * d0.y + v0.z * d0.z + v0.w * d0.w
             + v1.x * d1.x + v1.y * d1.y + v1.z * d1.z + v1.w * d1.w;
}

// ---------------- gather layer 1: warp/node, 2 edges per step --------------
__global__ __launch_bounds__(256)
void gather1_kernel(const float* __restrict__ b1, int N) {
    int w = (blockIdx.x * blockDim.x + threadIdx.x) >> 5;
    if (w >= N) return;
    int l    = threadIdx.x & 31;
    int half = l >> 4;
    int q    = l & 15;
    int h    = q >> 1;
    int d    = w;
    int beg = g_ptr[d], end = g_ptr[d + 1];

    float ad = g_ad1[d * H1 + h];

    float ax = 0.f, ay = 0.f, az = 0.f, aw = 0.f, den = 0.f;
    int i = beg;
    for (; i + 4 <= end; i += 4) {             // 2 steps x 2 edges
        int s0 = g_csr[i + half];
        int s1 = g_csr[i + 2 + half];
        float a0 = g_as1[s0 * H1 + h];
        float a1 = g_as1[s1 * H1 + h];
        float4 f0 = *(const float4*)&g_h1[(size_t)s0 * D1 + 4 * q];
        float4 f1 = *(const float4*)&g_h1[(size_t)s1 * D1 + 4 * q];
        float t0 = a0 + ad; t0 = (t0 > 0.f) ? t0 : 0.2f * t0;
        float t1 = a1 + ad; t1 = (t1 > 0.f) ? t1 : 0.2f * t1;
        float e0 = __expf(t0), e1 = __expf(t1);
        ax += e0 * f0.x + e1 * f1.x;
        ay += e0 * f0.y + e1 * f1.y;
        az += e0 * f0.z + e1 * f1.z;
        aw += e0 * f0.w + e1 * f1.w;
        den += e0 + e1;
    }
    for (; i < end; i += 2) {                  // tail: 1 or 2 edges
        int has2 = (i + 1 < end) ? 1 : 0;
        int s = g_csr[i + (half & has2)];
        float a = g_as1[s * H1 + h];
        float4 f = *(const float4*)&g_h1[(size_t)s * D1 + 4 * q];
        float t = a + ad; t = (t > 0.f) ? t : 0.2f * t;
        float ex = __expf(t);
        if (half && !has2) ex = 0.f;
        ax += ex * f.x; ay += ex * f.y; az += ex * f.z; aw += ex * f.w;
        den += ex;
    }
    ax  += __shfl_xor_sync(0xffffffffu, ax, 16);
    ay  += __shfl_xor_sync(0xffffffffu, ay, 16);
    az  += __shfl_xor_sync(0xffffffffu, az, 16);
    aw  += __shfl_xor_sync(0xffffffffu, aw, 16);
    den += __shfl_xor_sync(0xffffffffu, den, 16);
    if (half == 0) {
        float inv = 1.0f / (den + 1e-16f);
        float4 bb = *(const float4*)&b1[4 * q];
        float vx = ax * inv + bb.x;
        float vy = ay * inv + bb.y;
        float vz = az * inv + bb.z;
        float vw = aw * inv + bb.w;
        vx = (vx > 0.f) ? vx : (__expf(vx) - 1.f);
        vy = (vy > 0.f) ? vy : (__expf(vy) - 1.f);
        vz = (vz > 0.f) ? vz : (__expf(vz) - 1.f);
        vw = (vw > 0.f) ? vw : (__expf(vw) - 1.f);
        *(float4*)&g_h2[(size_t)d * D1 + 4 * q] = make_float4(vx, vy, vz, vw);
    }
}

// ---------------- GEMM2 + alpha2: g2[N,40] = h2[N,64]@W2[64,40] ------------
__global__ __launch_bounds__(256)
void gemm2_kernel(const float* __restrict__ W2,
                  const float* __restrict__ a_src2,
                  const float* __restrict__ a_dst2, int N) {
    __shared__ float sh[64 * 65];
    __shared__ float sw2[64 * OUT];

    int tid = threadIdx.x;
    int n0  = blockIdx.x * 64;

    for (int t = tid; t < 64 * D1; t += 256) {
        int r = t >> 6, c = t & 63;
        int gn = n0 + r;
        sh[r * 65 + c] = (gn < N) ? g_h2[(size_t)gn * D1 + c] : 0.0f;
    }
    for (int t = tid; t < D1 * OUT; t += 256) sw2[t] = W2[t];
    __syncthreads();

    int r = tid >> 2;
    int q = tid & 3;
    float acc[10];
#pragma unroll
    for (int j = 0; j < 10; j++) acc[j] = 0.0f;

#pragma unroll 8
    for (int k = 0; k < D1; k++) {
        float a = sh[r * 65 + k];
#pragma unroll
        for (int j = 0; j < 10; j++)
            acc[j] += a * sw2[k * OUT + q * 10 + j];
    }

    int gn = n0 + r;
    float ps = 0.0f, pd = 0.0f;
#pragma unroll
    for (int j = 0; j < 10; j++) {
        int c = q * 10 + j;
        ps += acc[j] * __ldg(&a_src2[c]);
        pd += acc[j] * __ldg(&a_dst2[c]);
        if (gn < N) g_g2[(size_t)gn * OUT + c] = acc[j];
    }
    ps += __shfl_down_sync(0xffffffffu, ps, 1, 4);
    ps += __shfl_down_sync(0xffffffffu, ps, 2, 4);
    pd += __shfl_down_sync(0xffffffffu, pd, 1, 4);
    pd += __shfl_down_sync(0xffffffffu, pd, 2, 4);
    if (q == 0 && gn < N) { g_as2[gn] = ps; g_ad2[gn] = pd; }
}

// ---------------- gather layer 2: warp/node, 3 edges per step --------------
__global__ __launch_bounds__(256)
void gather2_kernel(const float* __restrict__ b2, float* __restrict__ out, int N) {
    int w = (blockIdx.x * blockDim.x + threadIdx.x) >> 5;
    if (w >= N) return;
    int l = threadIdx.x & 31;
    bool act = (l < 30);
    int g = act ? (l / 10) : 0;
    int q = act ? (l - g * 10) : 0;
    int d = w;
    int beg = g_ptr[d], end = g_ptr[d + 1];

    float ad = g_ad2[d];
    float ax = 0.f, ay = 0.f, az = 0.f, aw = 0.f, den = 0.f;
    int i = beg;
    for (; i + 6 <= end; i += 6) {             // 2 steps x 3 edges
        int s0 = g_csr[i + g];
        int s1 = g_csr[i + 3 + g];
        float a0 = g_as2[s0], a1 = g_as2[s1];
        float4 f0 = *(const float4*)&g_g2[(size_t)s0 * OUT + 4 * q];
        float4 f1 = *(const float4*)&g_g2[(size_t)s1 * OUT + 4 * q];
        float t0 = a0 + ad; t0 = (t0 > 0.f) ? t0 : 0.2f * t0;
        float t1 = a1 + ad; t1 = (t1 > 0.f) ? t1 : 0.2f * t1;
        float e0 = __expf(t0), e1 = __expf(t1);
        if (!act) { e0 = 0.f; e1 = 0.f; }
        ax += e0 * f0.x + e1 * f1.x;
        ay += e0 * f0.y + e1 * f1.y;
        az += e0 * f0.z + e1 * f1.z;
        aw += e0 * f0.w + e1 * f1.w;
        den += e0 + e1;
    }
    for (; i < end; i += 3) {                  // tail
        int rem = end - i;
        int ok = act && (g < rem);
        int s = g_csr[i + (ok ? g : 0)];
        float a = g_as2[s];
        float4 f = *(const float4*)&g_g2[(size_t)s * OUT + 4 * q];
        float t = a + ad; t = (t > 0.f) ? t : 0.2f * t;
        float ex = __expf(t);
        if (!ok) ex = 0.f;
        ax += ex * f.x; ay += ex * f.y; az += ex * f.z; aw += ex * f.w;
        den += ex;
    }
    float bx1 = __shfl_down_sync(0xffffffffu, ax, 10);
    float bx2 = __shfl_down_sync(0xffffffffu, ax, 20);
    float by1 = __shfl_down_sync(0xffffffffu, ay, 10);
    float by2 = __shfl_down_sync(0xffffffffu, ay, 20);
    float bz1 = __shfl_down_sync(0xffffffffu, az, 10);
    float bz2 = __shfl_down_sync(0xffffffffu, az, 20);
    float bw1 = __shfl_down_sync(0xffffffffu, aw, 10);
    float bw2 = __shfl_down_sync(0xffffffffu, aw, 20);
    float bd1 = __shfl_down_sync(0xffffffffu, den, 10);
    float bd2 = __shfl_down_sync(0xffffffffu, den, 20);
    if (l < 10) {
        ax += bx1 + bx2; ay += by1 + by2; az += bz1 + bz2; aw += bw1 + bw2;
        den += bd1 + bd2;
        float inv = 1.0f / (den + 1e-16f);
        float4 bb = *(const float4*)&b2[4 * q];
        out[(size_t)d * OUT + 4 * q + 0] = ax * inv + bb.x;
        out[(size_t)d * OUT + 4 * q + 1] = ay * inv + bb.y;
        out[(size_t)d * OUT + 4 * q + 2] = az * inv + bb.z;
        out[(size_t)d * OUT + 4 * q + 3] = aw * inv + bb.w;
    }
}

// ---------------- launch ----------------
extern "C" void kernel_launch(void* const* d_in, const int* in_sizes, int n_in,
                              void* d_out, int out_size) {
    const float* x      = (const float*)d_in[0];
    const int*   ei     = (const int*)d_in[1];
    const float* W1     = (const float*)d_in[2];
    const float* a_src1 = (const float*)d_in[3];
    const float* a_dst1 = (const float*)d_in[4];
    const float* b1     = (const float*)d_in[5];
    const float* W2     = (const float*)d_in[6];
    const float* a_src2 = (const float*)d_in[7];
    const float* a_dst2 = (const float*)d_in[8];
    const float* b2     = (const float*)d_in[9];
    float* out = (float*)d_out;

    int N    = in_sizes[0] / F_IN;       // 100000
    int E    = in_sizes[1] / 2;          // 3200000
    int Etot = E + N;
    int nb   = (N + 255) / 256;

    wt_kernel<<<(F_IN * D1 + 255) / 256, 256>>>(W1);          // 0
    init_kernel<<<(N + 255) / 256, 256>>>(N);                 // 1
    hist_kernel<<<(E + 255) / 256, 256>>>(ei, E);             // 2
    gemm1_kernel<<<(N + 127) / 128, 256>>>(x, N);             // 3  <- profiled
    scan1_kernel<<<nb, 256>>>(N);                             // 4
    scan2_kernel<<<1, 512>>>(nb);                             // 5
    scan3_kernel<<<nb, 256>>>(N, Etot);                       // 6
    scatter_kernel<<<(Etot + 255) / 256, 256>>>(ei, E, Etot); // 7
    alpha1_kernel<<<(N * H1 + 255) / 256, 256>>>(a_src1, a_dst1, N); // 8
    gather1_kernel<<<(N * 32 + 255) / 256, 256>>>(b1, N);     // 9
    gemm2_kernel<<<(N + 63) / 64, 256>>>(W2, a_src2, a_dst2, N); // 10
    gather2_kernel<<<(N * 32 + 255) / 256, 256>>>(b2, out, N);   // 11
}